// round 1
// baseline (speedup 1.0000x reference)
#include <cuda_runtime.h>
#include <cstdint>

// y[b] = a_0 + sum_k bk[k] * tanh( dot(ck[k,:], z[b,:]) + dk[k] )
// B = 2097152, Z = 16, K = 64.  FP32 in / FP32 out.
//
// Strategy: packed f32x2 FMAs (2x FP32 throughput on sm_103a) + MUFU.TANH.
// Each thread processes EPT=4 consecutive batch rows as 2 f32x2 lane-pairs,
// with 2 partial-sum chains per pair for ILP. ck is staged in shared memory
// as duplicated (c,c) pairs so a single LDS.64 broadcast feeds both halves.

#define KK  64
#define ZZ  16
#define TPB 256
#define EPT 4

static __device__ __forceinline__ unsigned long long pack2(float lo, float hi) {
    unsigned long long r;
    asm("mov.b64 %0, {%1, %2};" : "=l"(r) : "f"(lo), "f"(hi));
    return r;
}
static __device__ __forceinline__ void unpack2(unsigned long long v, float& lo, float& hi) {
    asm("mov.b64 {%0, %1}, %2;" : "=f"(lo), "=f"(hi) : "l"(v));
}
static __device__ __forceinline__ unsigned long long fma2(unsigned long long a,
                                                          unsigned long long b,
                                                          unsigned long long c) {
    unsigned long long d;
    asm("fma.rn.f32x2 %0, %1, %2, %3;" : "=l"(d) : "l"(a), "l"(b), "l"(c));
    return d;
}
static __device__ __forceinline__ unsigned long long add2(unsigned long long a,
                                                          unsigned long long b) {
    unsigned long long d;
    asm("add.rn.f32x2 %0, %1, %2;" : "=l"(d) : "l"(a), "l"(b));
    return d;
}
static __device__ __forceinline__ float tanh_fast(float x) {
    float y;
    asm("tanh.approx.f32 %0, %1;" : "=f"(y) : "f"(x));
    return y;
}

__global__ __launch_bounds__(TPB, 2)
void mave_ge_kernel(const float4* __restrict__ z4,
                    const float*  __restrict__ a0,
                    const float*  __restrict__ bkp,
                    const float*  __restrict__ ckp,
                    const float*  __restrict__ dkp,
                    float*        __restrict__ out,
                    long long B)
{
    __shared__ unsigned long long c2[KK * ZZ];  // duplicated (c,c) pairs, 8 KB
    __shared__ float sbk[KK];
    __shared__ float sdk[KK];

    const int tid = threadIdx.x;
    for (int i = tid; i < KK * ZZ; i += TPB) {
        float c = ckp[i];
        c2[i] = pack2(c, c);
    }
    if (tid < KK) {
        sbk[tid] = bkp[tid];
        sdk[tid] = dkp[tid];
    }
    __syncthreads();

    const float a0v = a0[0];

    const long long e0 = ((long long)blockIdx.x * TPB + tid) * (long long)EPT;
    if (e0 >= B) return;
    const bool full = (e0 + EPT <= B);

    // ---- load z rows: EPT rows x 16 floats (4 float4 each), clamp at tail ----
    float zr[EPT][ZZ];
    #pragma unroll
    for (int r = 0; r < EPT; r++) {
        long long row = e0 + r;
        if (row > B - 1) row = B - 1;  // clamped duplicate at the tail (store guarded)
        const float4* p = z4 + row * (ZZ / 4);
        #pragma unroll
        for (int j = 0; j < 4; j++) {
            float4 v = p[j];
            zr[r][4 * j + 0] = v.x;
            zr[r][4 * j + 1] = v.y;
            zr[r][4 * j + 2] = v.z;
            zr[r][4 * j + 3] = v.w;
        }
    }

    // ---- pack rows (0,1) and (2,3) into f32x2 lanes ----
    unsigned long long zp0[ZZ], zp1[ZZ];
    #pragma unroll
    for (int j = 0; j < ZZ; j++) {
        zp0[j] = pack2(zr[0][j], zr[1][j]);
        zp1[j] = pack2(zr[2][j], zr[3][j]);
    }

    float acc0 = a0v, acc1 = a0v, acc2 = a0v, acc3 = a0v;

    #pragma unroll 4
    for (int k = 0; k < KK; k++) {
        const float dv = sdk[k];
        const unsigned long long d2 = pack2(dv, dv);
        const unsigned long long* crow = &c2[k * ZZ];

        // 4 independent FFMA2 chains (2 per lane-pair) for ILP
        unsigned long long s0a = d2, s0b = 0, s1a = d2, s1b = 0;
        #pragma unroll
        for (int j = 0; j < ZZ; j += 2) {
            unsigned long long ca = crow[j];
            unsigned long long cb = crow[j + 1];
            s0a = fma2(zp0[j],     ca, s0a);
            s0b = fma2(zp0[j + 1], cb, s0b);
            s1a = fma2(zp1[j],     ca, s1a);
            s1b = fma2(zp1[j + 1], cb, s1b);
        }
        unsigned long long s0 = add2(s0a, s0b);
        unsigned long long s1 = add2(s1a, s1b);

        float h0, h1, h2, h3;
        unpack2(s0, h0, h1);
        unpack2(s1, h2, h3);

        const float bv = sbk[k];
        acc0 = fmaf(bv, tanh_fast(h0), acc0);
        acc1 = fmaf(bv, tanh_fast(h1), acc1);
        acc2 = fmaf(bv, tanh_fast(h2), acc2);
        acc3 = fmaf(bv, tanh_fast(h3), acc3);
    }

    if (full) {
        float4 o = make_float4(acc0, acc1, acc2, acc3);
        *reinterpret_cast<float4*>(out + e0) = o;
    } else {
        float a[EPT] = {acc0, acc1, acc2, acc3};
        #pragma unroll
        for (int r = 0; r < EPT; r++)
            if (e0 + r < B) out[e0 + r] = a[r];
    }
}

extern "C" void kernel_launch(void* const* d_in, const int* in_sizes, int n_in,
                              void* d_out, int out_size) {
    const float* z  = (const float*)d_in[0];
    const float* a0 = (const float*)d_in[1];
    const float* bk = (const float*)d_in[2];
    const float* ck = (const float*)d_in[3];
    const float* dk = (const float*)d_in[4];
    float* out = (float*)d_out;

    const long long B = (long long)in_sizes[0] / ZZ;
    const long long rows_per_block = (long long)TPB * EPT;
    const int grid = (int)((B + rows_per_block - 1) / rows_per_block);

    mave_ge_kernel<<<grid, TPB>>>((const float4*)z, a0, bk, ck, dk, out, B);
}

// round 3
// speedup vs baseline: 1.8059x; 1.8059x over previous
#include <cuda_runtime.h>
#include <cuda_bf16.h>
#include <cstdint>

// y[b] = a_0 + sum_n bk[n] * tanh( dot(ck[n,:], z[b,:]) + dk[n] )
// B = 2097152, Z = 16, N = 64.
//
// HMMA path (mma.sync works on plain sm_103 target; tcgen05 does not compile
// in this harness). Per warp-iteration: 16 batch rows x 64 nodes via
// mma.sync.m16n8k16 bf16 with bf16x3 split (zh*ch + zl*ch + zh*cl), fp32
// accum, dk folded into the C-operand init. Epilogue: MUFU tanh + bk FFMA,
// quad shfl-reduce over the 4 column-threads.

#define ZD    16
#define NN    64
#define TPB   256
#define WPB   8        // warps per block
#define GRIDB 1024
#define CHUNK 16       // batch rows per warp-iteration

static __device__ __forceinline__ float tanh_fast(float x) {
    float y; asm("tanh.approx.f32 %0, %1;" : "=f"(y) : "f"(x)); return y;
}
// packed bf16x2: low half = bf16(lo), high half = bf16(hi)
static __device__ __forceinline__ uint32_t pack_bf16x2(float lo, float hi) {
    uint32_t r; asm("cvt.rn.bf16x2.f32 %0, %1, %2;" : "=r"(r) : "f"(hi), "f"(lo)); return r;
}
static __device__ __forceinline__ float bf_lo_f(uint32_t h) { return __uint_as_float(h << 16); }
static __device__ __forceinline__ float bf_hi_f(uint32_t h) { return __uint_as_float(h & 0xFFFF0000u); }

// hi/lo bf16 split of a float pair -> (hi_packed, lo_packed)
static __device__ __forceinline__ void split2(float x, float y, uint32_t& h, uint32_t& l) {
    h = pack_bf16x2(x, y);
    l = pack_bf16x2(x - bf_lo_f(h), y - bf_hi_f(h));
}

// D(f32) += A(bf16) * B(bf16), C aliased with D
static __device__ __forceinline__ void mma_bf16(
    float& d0, float& d1, float& d2, float& d3,
    uint32_t a0, uint32_t a1, uint32_t a2, uint32_t a3,
    uint32_t b0, uint32_t b1)
{
    asm volatile(
        "mma.sync.aligned.m16n8k16.row.col.f32.bf16.bf16.f32 "
        "{%0,%1,%2,%3}, {%4,%5,%6,%7}, {%8,%9}, {%0,%1,%2,%3};"
        : "+f"(d0), "+f"(d1), "+f"(d2), "+f"(d3)
        : "r"(a0), "r"(a1), "r"(a2), "r"(a3), "r"(b0), "r"(b1));
}

__global__ __launch_bounds__(TPB, 2)
void mave_hmma_kernel(const float* __restrict__ z,
                      const float* __restrict__ a0p,
                      const float* __restrict__ bkp,
                      const float* __restrict__ ckp,
                      const float* __restrict__ dkp,
                      float*       __restrict__ out,
                      long long B, int nchunks)
{
    __shared__ float sbk[NN];
    __shared__ float sdk[NN];

    const int tid  = threadIdx.x;
    if (tid < NN) { sbk[tid] = bkp[tid]; sdk[tid] = dkp[tid]; }
    __syncthreads();

    const int lane = tid & 31;
    const int g    = lane >> 2;   // groupID: row within 8-row half / B-col
    const int tg   = lane & 3;    // thread-in-group: k-pair / D-col pair

    // ---- B fragments from ck: 8 N-tiles, hi/lo bf16 split (32 regs) ----
    // b0 of tile j: B[k=2tg,2tg+1][n=8j+g] = ck[8j+g][2tg,2tg+1]; b1: k+8.
    uint32_t bh[16], bl[16];
    #pragma unroll
    for (int j = 0; j < 8; j++) {
        const float2* cp = reinterpret_cast<const float2*>(ckp + (8 * j + g) * ZD);
        float2 x0 = cp[tg];
        float2 x1 = cp[tg + 4];
        split2(x0.x, x0.y, bh[2 * j],     bl[2 * j]);
        split2(x1.x, x1.y, bh[2 * j + 1], bl[2 * j + 1]);
    }
    const float a0v = a0p[0];

    const int warp0  = blockIdx.x * WPB + (tid >> 5);
    const int nwarps = GRIDB * WPB;
    const float2* zp = reinterpret_cast<const float2*>(z);

    for (int c = warp0; c < nchunks; c += nwarps) {
        const long long base = (long long)c * CHUNK;
        // rows this thread touches (clamped for a possible tail chunk)
        long long r0 = base + g;
        long long r1 = base + g + 8;
        if (r0 >= B) r0 = B - 1;
        if (r1 >= B) r1 = B - 1;

        // ---- A fragments: a0:(r0, k=2tg..), a1:(r1, same), a2:(r0, k+8..), a3:(r1, k+8..)
        float2 x00 = zp[r0 * 8 + tg];
        float2 x10 = zp[r1 * 8 + tg];
        float2 x01 = zp[r0 * 8 + tg + 4];
        float2 x11 = zp[r1 * 8 + tg + 4];
        uint32_t ah0, al0, ah1, al1, ah2, al2, ah3, al3;
        split2(x00.x, x00.y, ah0, al0);
        split2(x10.x, x10.y, ah1, al1);
        split2(x01.x, x01.y, ah2, al2);
        split2(x11.x, x11.y, ah3, al3);

        float acc_lo = 0.0f, acc_hi = 0.0f;

        #pragma unroll
        for (int j = 0; j < 8; j++) {
            // C init = dk for this thread's two columns (rows share columns)
            float2 dpair = *reinterpret_cast<const float2*>(&sdk[8 * j + 2 * tg]);
            float d0 = dpair.x, d1 = dpair.y, d2 = dpair.x, d3 = dpair.y;

            mma_bf16(d0, d1, d2, d3, ah0, ah1, ah2, ah3, bh[2 * j], bh[2 * j + 1]);
            mma_bf16(d0, d1, d2, d3, al0, al1, al2, al3, bh[2 * j], bh[2 * j + 1]);
            mma_bf16(d0, d1, d2, d3, ah0, ah1, ah2, ah3, bl[2 * j], bl[2 * j + 1]);

            float2 bpair = *reinterpret_cast<const float2*>(&sbk[8 * j + 2 * tg]);
            acc_lo = fmaf(bpair.x, tanh_fast(d0), acc_lo);
            acc_lo = fmaf(bpair.y, tanh_fast(d1), acc_lo);
            acc_hi = fmaf(bpair.x, tanh_fast(d2), acc_hi);
            acc_hi = fmaf(bpair.y, tanh_fast(d3), acc_hi);
        }

        // ---- reduce over the 4 column-threads of each row ----
        acc_lo += __shfl_xor_sync(0xFFFFFFFFu, acc_lo, 1);
        acc_lo += __shfl_xor_sync(0xFFFFFFFFu, acc_lo, 2);
        acc_hi += __shfl_xor_sync(0xFFFFFFFFu, acc_hi, 1);
        acc_hi += __shfl_xor_sync(0xFFFFFFFFu, acc_hi, 2);

        if (tg == 0) {
            if (base + g < B)     out[base + g]     = a0v + acc_lo;
            if (base + g + 8 < B) out[base + g + 8] = a0v + acc_hi;
        }
    }
}

extern "C" void kernel_launch(void* const* d_in, const int* in_sizes, int n_in,
                              void* d_out, int out_size) {
    const float* z  = (const float*)d_in[0];
    const float* a0 = (const float*)d_in[1];
    const float* bk = (const float*)d_in[2];
    const float* ck = (const float*)d_in[3];
    const float* dk = (const float*)d_in[4];
    float* out = (float*)d_out;

    const long long B = (long long)in_sizes[0] / ZD;
    const int nchunks = (int)((B + CHUNK - 1) / CHUNK);

    mave_hmma_kernel<<<GRIDB, TPB>>>(z, a0, bk, ck, dk, out, B, nchunks);
}

// round 6
// speedup vs baseline: 2.4028x; 1.3306x over previous
#include <cuda_runtime.h>
#include <cuda_bf16.h>
#include <cstdint>

// y[b] = a_0 + sum_n bk[n] * tanh( dot(ck[n,:], z[b,:]) + dk[n] )
// B = 2097152, Z = 16, N = 64.
//
// HMMA m16n8k16 bf16 with bf16x3 split (zh*ch + zl*ch + zh*cl), fp32 accum,
// dk folded into C init. This round: software-pipelined grid-stride loop —
// the next chunk's z is prefetched into registers while the current chunk's
// MMAs + tanh epilogue execute, hiding DRAM latency. 32-bit indexing.

#define ZD    16
#define NN    64
#define TPB   256
#define WPB   8        // warps per block
#define GRIDB 1024
#define CHUNK 16       // batch rows per warp-iteration

static __device__ __forceinline__ float tanh_fast(float x) {
    float y; asm("tanh.approx.f32 %0, %1;" : "=f"(y) : "f"(x)); return y;
}
// packed bf16x2: low half = bf16(lo), high half = bf16(hi)
static __device__ __forceinline__ uint32_t pack_bf16x2(float lo, float hi) {
    uint32_t r; asm("cvt.rn.bf16x2.f32 %0, %1, %2;" : "=r"(r) : "f"(hi), "f"(lo)); return r;
}
static __device__ __forceinline__ float bf_lo_f(uint32_t h) { return __uint_as_float(h << 16); }
static __device__ __forceinline__ float bf_hi_f(uint32_t h) { return __uint_as_float(h & 0xFFFF0000u); }

static __device__ __forceinline__ void split2(float x, float y, uint32_t& h, uint32_t& l) {
    h = pack_bf16x2(x, y);
    l = pack_bf16x2(x - bf_lo_f(h), y - bf_hi_f(h));
}

static __device__ __forceinline__ void mma_bf16(
    float& d0, float& d1, float& d2, float& d3,
    uint32_t a0, uint32_t a1, uint32_t a2, uint32_t a3,
    uint32_t b0, uint32_t b1)
{
    asm volatile(
        "mma.sync.aligned.m16n8k16.row.col.f32.bf16.bf16.f32 "
        "{%0,%1,%2,%3}, {%4,%5,%6,%7}, {%8,%9}, {%0,%1,%2,%3};"
        : "+f"(d0), "+f"(d1), "+f"(d2), "+f"(d3)
        : "r"(a0), "r"(a1), "r"(a2), "r"(a3), "r"(b0), "r"(b1));
}

__global__ __launch_bounds__(TPB, 2)
void mave_hmma_kernel(const float2* __restrict__ zp,
                      const float* __restrict__ a0p,
                      const float* __restrict__ bkp,
                      const float* __restrict__ ckp,
                      const float* __restrict__ dkp,
                      float*       __restrict__ out,
                      int B, int nchunks)
{
    __shared__ float sbk[NN];
    __shared__ float sdk[NN];

    const int tid = threadIdx.x;
    if (tid < NN) { sbk[tid] = bkp[tid]; sdk[tid] = dkp[tid]; }
    __syncthreads();

    const int lane = tid & 31;
    const int g    = lane >> 2;   // groupID: row within 8-row half / B-col
    const int tg   = lane & 3;    // thread-in-group: k-pair / D-col pair

    // ---- B fragments from ck: 8 N-tiles, hi/lo bf16 split (32 regs) ----
    uint32_t bh[16], bl[16];
    #pragma unroll
    for (int j = 0; j < 8; j++) {
        const float2* cp = reinterpret_cast<const float2*>(ckp + (8 * j + g) * ZD);
        float2 x0 = cp[tg];
        float2 x1 = cp[tg + 4];
        split2(x0.x, x0.y, bh[2 * j],     bl[2 * j]);
        split2(x1.x, x1.y, bh[2 * j + 1], bl[2 * j + 1]);
    }
    const float a0v = a0p[0];

    const int warp0  = blockIdx.x * WPB + (tid >> 5);
    const int nwarps = GRIDB * WPB;

    int c = warp0;
    if (c >= nchunks) return;

    // ---- prime the pipeline: load chunk c's z rows (raw float2s) ----
    float2 x00, x10, x01, x11;
    {
        int base = c * CHUNK;
        int r0 = base + g;     if (r0 > B - 1) r0 = B - 1;
        int r1 = base + g + 8; if (r1 > B - 1) r1 = B - 1;
        x00 = zp[r0 * 8 + tg];
        x10 = zp[r1 * 8 + tg];
        x01 = zp[r0 * 8 + tg + 4];
        x11 = zp[r1 * 8 + tg + 4];
    }

    while (c < nchunks) {
        // ---- consume the buffer: bf16 hi/lo split into A fragments ----
        uint32_t ah0, al0, ah1, al1, ah2, al2, ah3, al3;
        split2(x00.x, x00.y, ah0, al0);
        split2(x10.x, x10.y, ah1, al1);
        split2(x01.x, x01.y, ah2, al2);
        split2(x11.x, x11.y, ah3, al3);

        const int base = c * CHUNK;
        const int cn = c + nwarps;

        // ---- prefetch next chunk's z; overlaps the MMAs + epilogue below ----
        if (cn < nchunks) {
            int nb = cn * CHUNK;
            int r0 = nb + g;     if (r0 > B - 1) r0 = B - 1;
            int r1 = nb + g + 8; if (r1 > B - 1) r1 = B - 1;
            x00 = zp[r0 * 8 + tg];
            x10 = zp[r1 * 8 + tg];
            x01 = zp[r0 * 8 + tg + 4];
            x11 = zp[r1 * 8 + tg + 4];
        }

        float acc_lo = 0.0f, acc_hi = 0.0f;

        #pragma unroll
        for (int j = 0; j < 8; j++) {
            float2 dpair = *reinterpret_cast<const float2*>(&sdk[8 * j + 2 * tg]);
            float d0 = dpair.x, d1 = dpair.y, d2 = dpair.x, d3 = dpair.y;

            mma_bf16(d0, d1, d2, d3, ah0, ah1, ah2, ah3, bh[2 * j], bh[2 * j + 1]);
            mma_bf16(d0, d1, d2, d3, al0, al1, al2, al3, bh[2 * j], bh[2 * j + 1]);
            mma_bf16(d0, d1, d2, d3, ah0, ah1, ah2, ah3, bl[2 * j], bl[2 * j + 1]);

            float2 bpair = *reinterpret_cast<const float2*>(&sbk[8 * j + 2 * tg]);
            acc_lo = fmaf(bpair.x, tanh_fast(d0), acc_lo);
            acc_lo = fmaf(bpair.y, tanh_fast(d1), acc_lo);
            acc_hi = fmaf(bpair.x, tanh_fast(d2), acc_hi);
            acc_hi = fmaf(bpair.y, tanh_fast(d3), acc_hi);
        }

        // ---- reduce over the 4 column-threads of each row ----
        acc_lo += __shfl_xor_sync(0xFFFFFFFFu, acc_lo, 1);
        acc_lo += __shfl_xor_sync(0xFFFFFFFFu, acc_lo, 2);
        acc_hi += __shfl_xor_sync(0xFFFFFFFFu, acc_hi, 1);
        acc_hi += __shfl_xor_sync(0xFFFFFFFFu, acc_hi, 2);

        if (tg == 0) {
            if (base + g < B)     out[base + g]     = a0v + acc_lo;
            if (base + g + 8 < B) out[base + g + 8] = a0v + acc_hi;
        }
        c = cn;
    }
}

extern "C" void kernel_launch(void* const* d_in, const int* in_sizes, int n_in,
                              void* d_out, int out_size) {
    const float* z  = (const float*)d_in[0];
    const float* a0 = (const float*)d_in[1];
    const float* bk = (const float*)d_in[2];
    const float* ck = (const float*)d_in[3];
    const float* dk = (const float*)d_in[4];
    float* out = (float*)d_out;

    const int B = in_sizes[0] / ZD;
    const int nchunks = (B + CHUNK - 1) / CHUNK;

    mave_hmma_kernel<<<GRIDB, TPB>>>((const float2*)z, a0, bk, ck, dk, out, B, nchunks);
}

// round 10
// speedup vs baseline: 2.6151x; 1.0883x over previous
#include <cuda_runtime.h>
#include <cuda_bf16.h>
#include <cstdint>

// y[b] = a_0 + sum_n bk[n] * tanh( dot(ck[n,:], z[b,:]) + dk[n] )
// B = 2097152, Z = 16, N = 64.
//
// HMMA m16n8k16 bf16, bf16x3 split (zh*ch + zl*ch + zh*cl), fp32 accum, dk in
// C init. This round: occupancy 2->3 CTAs/SM by moving the 32-reg B-fragment
// set into SMEM (pre-swizzled per-lane layout, one LDS.128 per j-tile), plus
// grid = 148*3 = one resident persistent wave.

#define ZD    16
#define NN    64
#define TPB   256
#define WPB   8        // warps per block
#define GRIDB 444      // 148 SMs * 3 CTAs -> exactly one wave
#define CHUNK 16       // batch rows per warp-iteration

static __device__ __forceinline__ float tanh_fast(float x) {
    float y; asm("tanh.approx.f32 %0, %1;" : "=f"(y) : "f"(x)); return y;
}
// packed bf16x2: low half = bf16(lo), high half = bf16(hi)
static __device__ __forceinline__ uint32_t pack_bf16x2(float lo, float hi) {
    uint32_t r; asm("cvt.rn.bf16x2.f32 %0, %1, %2;" : "=r"(r) : "f"(hi), "f"(lo)); return r;
}
static __device__ __forceinline__ float bf_lo_f(uint32_t h) { return __uint_as_float(h << 16); }
static __device__ __forceinline__ float bf_hi_f(uint32_t h) { return __uint_as_float(h & 0xFFFF0000u); }

static __device__ __forceinline__ void split2(float x, float y, uint32_t& h, uint32_t& l) {
    h = pack_bf16x2(x, y);
    l = pack_bf16x2(x - bf_lo_f(h), y - bf_hi_f(h));
}

static __device__ __forceinline__ void mma_bf16(
    float& d0, float& d1, float& d2, float& d3,
    uint32_t a0, uint32_t a1, uint32_t a2, uint32_t a3,
    uint32_t b0, uint32_t b1)
{
    asm volatile(
        "mma.sync.aligned.m16n8k16.row.col.f32.bf16.bf16.f32 "
        "{%0,%1,%2,%3}, {%4,%5,%6,%7}, {%8,%9}, {%0,%1,%2,%3};"
        : "+f"(d0), "+f"(d1), "+f"(d2), "+f"(d3)
        : "r"(a0), "r"(a1), "r"(a2), "r"(a3), "r"(b0), "r"(b1));
}

__global__ __launch_bounds__(TPB, 3)
void mave_hmma_kernel(const float2* __restrict__ zp,
                      const float* __restrict__ a0p,
                      const float* __restrict__ bkp,
                      const float* __restrict__ ckp,
                      const float* __restrict__ dkp,
                      float*       __restrict__ out,
                      int B, int nchunks)
{
    __shared__ float sbk[NN];
    __shared__ float sdk[NN];
    __shared__ uint4 sfrag[8][32];   // [j][lane] = (bh0, bh1, bl0, bl1), 4 KB

    const int tid  = threadIdx.x;
    const int wid  = tid >> 5;
    const int lane = tid & 31;
    const int g    = lane >> 2;   // groupID: row within 8-row half / B-col
    const int tg   = lane & 3;    // thread-in-group: k-pair / D-col pair

    if (tid < NN) { sbk[tid] = bkp[tid]; sdk[tid] = dkp[tid]; }

    // ---- warp w builds the B fragment for j = w (identical across blocks) ----
    {
        const int j = wid;
        const float2* cp = reinterpret_cast<const float2*>(ckp + (8 * j + g) * ZD);
        float2 x0 = cp[tg];
        float2 x1 = cp[tg + 4];
        uint32_t h0, l0, h1, l1;
        split2(x0.x, x0.y, h0, l0);
        split2(x1.x, x1.y, h1, l1);
        sfrag[j][lane] = make_uint4(h0, h1, l0, l1);
    }
    __syncthreads();

    const float a0v = a0p[0];
    const int warp0  = blockIdx.x * WPB + wid;
    const int nwarps = GRIDB * WPB;

    int c = warp0;
    if (c >= nchunks) return;

    // ---- prime the pipeline: load chunk c's z rows (raw float2s) ----
    float2 x00, x10, x01, x11;
    {
        int base = c * CHUNK;
        int r0 = base + g;     if (r0 > B - 1) r0 = B - 1;
        int r1 = base + g + 8; if (r1 > B - 1) r1 = B - 1;
        x00 = zp[r0 * 8 + tg];
        x10 = zp[r1 * 8 + tg];
        x01 = zp[r0 * 8 + tg + 4];
        x11 = zp[r1 * 8 + tg + 4];
    }

    while (c < nchunks) {
        // ---- consume the buffer: bf16 hi/lo split into A fragments ----
        uint32_t ah0, al0, ah1, al1, ah2, al2, ah3, al3;
        split2(x00.x, x00.y, ah0, al0);
        split2(x10.x, x10.y, ah1, al1);
        split2(x01.x, x01.y, ah2, al2);
        split2(x11.x, x11.y, ah3, al3);

        const int base = c * CHUNK;
        const int cn = c + nwarps;

        // ---- prefetch next chunk's z; overlaps the MMAs + epilogue below ----
        if (cn < nchunks) {
            int nb = cn * CHUNK;
            int r0 = nb + g;     if (r0 > B - 1) r0 = B - 1;
            int r1 = nb + g + 8; if (r1 > B - 1) r1 = B - 1;
            x00 = zp[r0 * 8 + tg];
            x10 = zp[r1 * 8 + tg];
            x01 = zp[r0 * 8 + tg + 4];
            x11 = zp[r1 * 8 + tg + 4];
        }

        float acc_lo = 0.0f, acc_hi = 0.0f;

        #pragma unroll
        for (int j = 0; j < 8; j++) {
            uint4 f = sfrag[j][lane];   // one LDS.128: bh0, bh1, bl0, bl1

            float2 dpair = *reinterpret_cast<const float2*>(&sdk[8 * j + 2 * tg]);
            float d0 = dpair.x, d1 = dpair.y, d2 = dpair.x, d3 = dpair.y;

            mma_bf16(d0, d1, d2, d3, ah0, ah1, ah2, ah3, f.x, f.y);
            mma_bf16(d0, d1, d2, d3, al0, al1, al2, al3, f.x, f.y);
            mma_bf16(d0, d1, d2, d3, ah0, ah1, ah2, ah3, f.z, f.w);

            float2 bpair = *reinterpret_cast<const float2*>(&sbk[8 * j + 2 * tg]);
            acc_lo = fmaf(bpair.x, tanh_fast(d0), acc_lo);
            acc_lo = fmaf(bpair.y, tanh_fast(d1), acc_lo);
            acc_hi = fmaf(bpair.x, tanh_fast(d2), acc_hi);
            acc_hi = fmaf(bpair.y, tanh_fast(d3), acc_hi);
        }

        // ---- reduce over the 4 column-threads of each row ----
        acc_lo += __shfl_xor_sync(0xFFFFFFFFu, acc_lo, 1);
        acc_lo += __shfl_xor_sync(0xFFFFFFFFu, acc_lo, 2);
        acc_hi += __shfl_xor_sync(0xFFFFFFFFu, acc_hi, 1);
        acc_hi += __shfl_xor_sync(0xFFFFFFFFu, acc_hi, 2);

        if (tg == 0) {
            if (base + g < B)     out[base + g]     = a0v + acc_lo;
            if (base + g + 8 < B) out[base + g + 8] = a0v + acc_hi;
        }
        c = cn;
    }
}

extern "C" void kernel_launch(void* const* d_in, const int* in_sizes, int n_in,
                              void* d_out, int out_size) {
    const float* z  = (const float*)d_in[0];
    const float* a0 = (const float*)d_in[1];
    const float* bk = (const float*)d_in[2];
    const float* ck = (const float*)d_in[3];
    const float* dk = (const float*)d_in[4];
    float* out = (float*)d_out;

    const int B = in_sizes[0] / ZD;
    const int nchunks = (B + CHUNK - 1) / CHUNK;

    mave_hmma_kernel<<<GRIDB, TPB>>>((const float2*)z, a0, bk, ck, dk, out, B, nchunks);
}